// round 7
// baseline (speedup 1.0000x reference)
#include <cuda_runtime.h>
#include <math.h>

#define N_ROWS 65536
#define D      512
#define NB     65536
#define NBLK   256
#define NTHR   256
#define CHUNK  256

// ---------------- scratch (device globals: zero-initialized at module load,
// and re-zeroed by the fused kernel at the end of every call) ----------------
__device__ float    g_e2[N_ROWS], g_e3[N_ROWS];
__device__ unsigned g_hist[NB], g_cnt[NB], g_off[NB];
__device__ unsigned long long g_bsort[N_ROWS];
__device__ float    g_se2[N_ROWS], g_se3[N_ROWS];
__device__ unsigned g_bsum[NBLK], g_boff[NBLK];
__device__ double   g_csum2[NBLK], g_csum3[NBLK], g_part[NBLK];
__device__ unsigned g_bar[8];     // grid-barrier counters (must end each call zeroed)
__device__ unsigned g_done;       // final-phase counter (ditto)

__device__ __forceinline__ unsigned bucket_of(float k) {
    k = fminf(fmaxf(k, 0.0f), 0.999999f);
    unsigned b = (unsigned)(k * 65536.0f);
    return b > 65535u ? 65535u : b;
}

// Grid barrier (single-wave kernel; CG-style release/acquire pattern).
__device__ __forceinline__ void gbar(int i) {
    __syncthreads();
    if (threadIdx.x == 0) {
        __threadfence();                      // release
        atomicAdd(&g_bar[i], 1u);
        while (((volatile unsigned*)g_bar)[i] < NBLK) __nanosleep(32);
        __threadfence();                      // acquire
    }
    __syncthreads();
}

// ===========================================================================
// K1: per-row cos-sim -> exp, fused ranking histogram, norms computed
// redundantly per block. 8192 blocks x 256 (1 warp/row). LTS-bandwidth bound.
// Requires g_hist zeroed on entry (module init / previous call's cleanup).
// ===========================================================================
__global__ void __launch_bounds__(256)
k1_main(const float4* __restrict__ x,
        const float4* __restrict__ o2,
        const float4* __restrict__ o3,
        const float*  __restrict__ rank) {
    __shared__ float4 so2[128], so3[128];
    __shared__ float  red[8];
    __shared__ float  s_n2, s_n3;
    int t = threadIdx.x;
    if (t < 128)      so2[t]       = o2[t];
    else              so3[t - 128] = o3[t - 128];
    __syncthreads();

    // redundant per-block norm of o2 (warps 0-3) and o3 (warps 4-7)
    float a;
    if (t < 128) { float4 v = so2[t];       a = v.x*v.x + v.y*v.y + v.z*v.z + v.w*v.w; }
    else         { float4 v = so3[t - 128]; a = v.x*v.x + v.y*v.y + v.z*v.z + v.w*v.w; }
#pragma unroll
    for (int o = 16; o > 0; o >>= 1) a += __shfl_xor_sync(0xFFFFFFFFu, a, o);
    int warp = t >> 5, lane = t & 31;
    if (lane == 0) red[warp] = a;
    __syncthreads();
    if (t == 0) {
        s_n2 = sqrtf(red[0] + red[1] + red[2] + red[3]);
        s_n3 = sqrtf(red[4] + red[5] + red[6] + red[7]);
    }
    __syncthreads();
    float n2 = s_n2, n3 = s_n3;

    int row = blockIdx.x * 8 + warp;
    const float4* xr = x + (size_t)row * 128;
    float d2 = 0.f, d3 = 0.f, nn = 0.f;
#pragma unroll
    for (int k = 0; k < 4; k++) {
        float4 v = xr[lane + 32 * k];
        float4 p = so2[lane + 32 * k];
        float4 q = so3[lane + 32 * k];
        d2 += v.x * p.x + v.y * p.y + v.z * p.z + v.w * p.w;
        d3 += v.x * q.x + v.y * q.y + v.z * q.z + v.w * q.w;
        nn += v.x * v.x + v.y * v.y + v.z * v.z + v.w * v.w;
    }
#pragma unroll
    for (int o = 16; o > 0; o >>= 1) {
        d2 += __shfl_xor_sync(0xFFFFFFFFu, d2, o);
        d3 += __shfl_xor_sync(0xFFFFFFFFu, d3, o);
        nn += __shfl_xor_sync(0xFFFFFFFFu, nn, o);
    }
    if (lane == 0) {
        float nx = sqrtf(nn);
        g_e2[row] = expf(d2 / fmaxf(nx * n2, 1e-8f));
        g_e3[row] = expf(d3 / fmaxf(nx * n3, 1e-8f));
        atomicAdd(&g_hist[bucket_of(rank[row])], 1u);
    }
}

// ===========================================================================
// K2 (fused): hist scan -> scatter -> place -> chunk sums -> scans -> logs
// -> final, with grid barriers. Single wave: 256 blocks x 256 threads.
// ===========================================================================
union ShU {
    unsigned su[NTHR];
    struct { double a[NTHR]; double b[NTHR]; } dd;
};

__global__ void __launch_bounds__(256, 2)
k2_fused(const float* __restrict__ rank, float* __restrict__ out) {
    __shared__ ShU sh;
    __shared__ double red8[8];
    int t = threadIdx.x, blk = blockIdx.x;
    int g = blk * NTHR + t;                  // 0..65535: element id / bucket id

    // ---- Phase A: global exclusive scan of g_hist --------------------------
    unsigned h = __ldcg(&g_hist[g]);
    sh.su[t] = h; __syncthreads();
#pragma unroll
    for (int o = 1; o < NTHR; o <<= 1) {
        unsigned v = (t >= o) ? sh.su[t - o] : 0u;
        __syncthreads();
        sh.su[t] += v;
        __syncthreads();
    }
    unsigned incl = sh.su[t];
    if (t == NTHR - 1) g_bsum[blk] = incl;
    unsigned exclb = incl - h;
    gbar(0);
    if (blk == 0) {                          // scan the 256 block sums
        unsigned b = __ldcg(&g_bsum[t]);
        sh.su[t] = b; __syncthreads();
#pragma unroll
        for (int o = 1; o < NTHR; o <<= 1) {
            unsigned v = (t >= o) ? sh.su[t - o] : 0u;
            __syncthreads();
            sh.su[t] += v;
            __syncthreads();
        }
        g_boff[t] = sh.su[t] - b;
    }
    gbar(1);
    unsigned off = __ldcg(&g_boff[blk]) + exclb;   // bucket g: base offset (kept in reg)
    g_off[g] = off;
    gbar(2);

    // ---- Phase B: scatter packed (key,idx) into bucket slots ---------------
    {
        float k = rank[g];
        unsigned b = bucket_of(k);
        unsigned slot = __ldcg(&g_off[b]) + atomicAdd(&g_cnt[b], 1u);
        g_bsort[slot] = ((unsigned long long)__float_as_uint(k) << 32) | (unsigned)g;
    }
    gbar(3);

    // ---- Phase C: within-bucket rank by u64 total order; then zero hist/cnt
    if (h != 0u) {
        unsigned base = off;
        if (h == 1u) {
            unsigned idx = (unsigned)(__ldcg(&g_bsort[base]) & 0xFFFFFFFFu);
            g_se2[base] = g_e2[idx];
            g_se3[base] = g_e3[idx];
        } else if (h <= 8u) {
            unsigned long long loc[8];
            for (unsigned j = 0; j < h; j++) loc[j] = __ldcg(&g_bsort[base + j]);
            for (unsigned j = 0; j < h; j++) {
                unsigned long long kj = loc[j];
                unsigned r = 0;
                for (unsigned l = 0; l < h; l++) r += (loc[l] < kj);
                unsigned idx = (unsigned)(kj & 0xFFFFFFFFu);
                g_se2[base + r] = g_e2[idx];
                g_se3[base + r] = g_e3[idx];
            }
        } else {                              // rare (Poisson(1) tail): L2 reads
            for (unsigned j = 0; j < h; j++) {
                unsigned long long kj = __ldcg(&g_bsort[base + j]);
                unsigned r = 0;
                for (unsigned l = 0; l < h; l++)
                    r += (__ldcg(&g_bsort[base + l]) < kj);
                unsigned idx = (unsigned)(kj & 0xFFFFFFFFu);
                g_se2[base + r] = g_e2[idx];
                g_se3[base + r] = g_e3[idx];
            }
        }
    }
    g_hist[g] = 0u;                          // cleanup for next call
    g_cnt[g]  = 0u;
    gbar(4);

    // ---- Phase D: per-chunk double sums (block blk == chunk blk) -----------
    double v2 = (double)__ldcg(&g_se2[g]);
    double v3 = (double)__ldcg(&g_se3[g]);
    {
        double a2 = v2, a3 = v3;
#pragma unroll
        for (int o = 16; o > 0; o >>= 1) {
            a2 += __shfl_xor_sync(0xFFFFFFFFu, a2, o);
            a3 += __shfl_xor_sync(0xFFFFFFFFu, a3, o);
        }
        __syncthreads();                      // sh union reuse safety
        if ((t & 31) == 0) { sh.dd.a[t >> 5] = a2; sh.dd.b[t >> 5] = a3; }
        __syncthreads();
        if (t == 0) {
            double s2 = 0.0, s3 = 0.0;
            for (int j = 0; j < 8; j++) { s2 += sh.dd.a[j]; s3 += sh.dd.b[j]; }
            g_csum2[blk] = s2; g_csum3[blk] = s3;
        }
    }
    gbar(5);

    // ---- Phase E: redundant chunk-offset scan + per-chunk scan + logs ------
    __syncthreads();
    sh.dd.a[t] = __ldcg(&g_csum2[t]);
    sh.dd.b[t] = __ldcg(&g_csum3[t]);
    __syncthreads();
#pragma unroll
    for (int o = 1; o < NTHR; o <<= 1) {
        double x2 = (t >= o) ? sh.dd.a[t - o] : 0.0;
        double x3 = (t >= o) ? sh.dd.b[t - o] : 0.0;
        __syncthreads();
        sh.dd.a[t] += x2; sh.dd.b[t] += x3;
        __syncthreads();
    }
    double tot2 = sh.dd.a[NTHR - 1], tot3 = sh.dd.b[NTHR - 1];
    double off2 = (blk > 0) ? sh.dd.a[blk - 1] : 0.0;
    double off3 = (blk > 0) ? sh.dd.b[blk - 1] : 0.0;
    __syncthreads();

    sh.dd.a[t] = v2; sh.dd.b[t] = v3;        // per-chunk inclusive scan
    __syncthreads();
#pragma unroll
    for (int o = 1; o < CHUNK; o <<= 1) {
        double x2 = (t >= o) ? sh.dd.a[t - o] : 0.0;
        double x3 = (t >= o) ? sh.dd.b[t - o] : 0.0;
        __syncthreads();
        sh.dd.a[t] += x2; sh.dd.b[t] += x3;
        __syncthreads();
    }
    double ls = (double)logf((float)(off2 + sh.dd.a[t])) +
                (double)logf((float)(off3 + sh.dd.b[t]));
#pragma unroll
    for (int o = 16; o > 0; o >>= 1) ls += __shfl_xor_sync(0xFFFFFFFFu, ls, o);
    if ((t & 31) == 0) red8[t >> 5] = ls;
    __syncthreads();
    if (t == 0) {
        double s = 0.0;
        for (int j = 0; j < 8; j++) s += red8[j];
        g_part[blk] = s;
    }

    // ---- Final: last block reduces partials, writes out, resets barriers ---
    __shared__ bool amLast;
    if (t == 0) {
        __threadfence();
        amLast = (atomicAdd(&g_done, 1u) == NBLK - 1);
    }
    __syncthreads();
    if (amLast) {
        double p = __ldcg(&g_part[t]);
#pragma unroll
        for (int o = 16; o > 0; o >>= 1) p += __shfl_xor_sync(0xFFFFFFFFu, p, o);
        __syncthreads();
        if ((t & 31) == 0) red8[t >> 5] = p;
        __syncthreads();
        if (t == 0) {
            double s = 0.0;
            for (int j = 0; j < 8; j++) s += red8[j];
            out[0] = (float)((double)N_ROWS * (log(tot2) + log(tot3)) - s);
            g_done = 0u;                      // all blocks incremented; safe
        }
        if (t < 8) g_bar[t] = 0u;             // all blocks released; safe
    }
}

extern "C" void kernel_launch(void* const* d_in, const int* in_sizes, int n_in,
                              void* d_out, int out_size) {
    const float* o1   = (const float*)d_in[0];  // [65536, 512]
    const float* o2   = (const float*)d_in[1];  // [1, 512]
    const float* o3   = (const float*)d_in[2];  // [1, 512]
    const float* rank = (const float*)d_in[3];  // [65536]
    float* out = (float*)d_out;

    k1_main<<<N_ROWS / 8, 256>>>((const float4*)o1, (const float4*)o2,
                                 (const float4*)o3, rank);
    k2_fused<<<NBLK, NTHR>>>(rank, out);
}

// round 8
// speedup vs baseline: 1.4033x; 1.4033x over previous
#include <cuda_runtime.h>
#include <math.h>

#define N_ROWS 65536
#define D      512
#define NB     65536
#define NBLK   64
#define NTHR   256
#define VT     4          // elements / buckets per thread

// ---------------- scratch (device globals: zero-init at load; the fused
// kernel re-zeroes everything it needs zeroed before it exits) --------------
__device__ float    g_e2[N_ROWS], g_e3[N_ROWS];
__device__ unsigned g_hist[NB], g_cnt[NB], g_off[NB];
__device__ unsigned long long g_bsort[N_ROWS];
__device__ float    g_se2[N_ROWS], g_se3[N_ROWS];
__device__ unsigned g_bsum[NBLK];
__device__ double   g_csum2[NBLK], g_csum3[NBLK], g_part[NBLK];
__device__ unsigned g_bar[8];
__device__ unsigned g_done;

__device__ __forceinline__ unsigned bucket_of(float k) {
    k = fminf(fmaxf(k, 0.0f), 0.999999f);
    unsigned b = (unsigned)(k * 65536.0f);
    return b > 65535u ? 65535u : b;
}

// Grid barrier across NBLK blocks (single wave guaranteed: 64 blocks).
__device__ __forceinline__ void gbar(int i) {
    __syncthreads();
    if (threadIdx.x == 0) {
        __threadfence();                       // release
        atomicAdd(&g_bar[i], 1u);
        while (((volatile unsigned*)g_bar)[i] < NBLK) __nanosleep(20);
        __threadfence();                       // acquire
    }
    __syncthreads();
}

// ===========================================================================
// K1: per-row cos-sim -> exp, fused ranking histogram, redundant norms.
// 8192 blocks x 256 (1 warp/row). LTS-bandwidth bound.
// ===========================================================================
__global__ void __launch_bounds__(256)
k1_main(const float4* __restrict__ x,
        const float4* __restrict__ o2,
        const float4* __restrict__ o3,
        const float*  __restrict__ rank) {
    __shared__ float4 so2[128], so3[128];
    __shared__ float  red[8];
    __shared__ float  s_n2, s_n3;
    int t = threadIdx.x;
    if (t < 128)      so2[t]       = o2[t];
    else              so3[t - 128] = o3[t - 128];
    __syncthreads();

    float a;
    if (t < 128) { float4 v = so2[t];       a = v.x*v.x + v.y*v.y + v.z*v.z + v.w*v.w; }
    else         { float4 v = so3[t - 128]; a = v.x*v.x + v.y*v.y + v.z*v.z + v.w*v.w; }
#pragma unroll
    for (int o = 16; o > 0; o >>= 1) a += __shfl_xor_sync(0xFFFFFFFFu, a, o);
    int warp = t >> 5, lane = t & 31;
    if (lane == 0) red[warp] = a;
    __syncthreads();
    if (t == 0) {
        s_n2 = sqrtf(red[0] + red[1] + red[2] + red[3]);
        s_n3 = sqrtf(red[4] + red[5] + red[6] + red[7]);
    }
    __syncthreads();
    float n2 = s_n2, n3 = s_n3;

    int row = blockIdx.x * 8 + warp;
    const float4* xr = x + (size_t)row * 128;
    float d2 = 0.f, d3 = 0.f, nn = 0.f;
#pragma unroll
    for (int k = 0; k < 4; k++) {
        float4 v = xr[lane + 32 * k];
        float4 p = so2[lane + 32 * k];
        float4 q = so3[lane + 32 * k];
        d2 += v.x * p.x + v.y * p.y + v.z * p.z + v.w * p.w;
        d3 += v.x * q.x + v.y * q.y + v.z * q.z + v.w * q.w;
        nn += v.x * v.x + v.y * v.y + v.z * v.z + v.w * v.w;
    }
#pragma unroll
    for (int o = 16; o > 0; o >>= 1) {
        d2 += __shfl_xor_sync(0xFFFFFFFFu, d2, o);
        d3 += __shfl_xor_sync(0xFFFFFFFFu, d3, o);
        nn += __shfl_xor_sync(0xFFFFFFFFu, nn, o);
    }
    if (lane == 0) {
        float nx = sqrtf(nn);
        g_e2[row] = expf(d2 / fmaxf(nx * n2, 1e-8f));
        g_e3[row] = expf(d3 / fmaxf(nx * n3, 1e-8f));
        atomicAdd(&g_hist[bucket_of(rank[row])], 1u);
    }
}

// ===========================================================================
// K2 (fused, 64 blocks x 256, VT=4): hist scan -> scatter -> place ->
// chunk sums -> prefix+logs -> final. 5 grid barriers.
// ===========================================================================
union ShU {
    unsigned su[NTHR];
    struct { double a[NTHR]; double b[NTHR]; } dd;
};

__global__ void __launch_bounds__(256)
k2_fused(const float* __restrict__ rank, float* __restrict__ out) {
    __shared__ ShU sh;
    __shared__ double red8a[8], red8b[8];
    int t = threadIdx.x, blk = blockIdx.x;
    int b0 = (blk * NTHR + t) * VT;          // first bucket / element id of this thread

    // ---- Phase A: exclusive scan of g_hist (65536 bins) --------------------
    uint4 hv = __ldcg((const uint4*)&g_hist[b0]);
    unsigned hsum = hv.x + hv.y + hv.z + hv.w;
    sh.su[t] = hsum; __syncthreads();
#pragma unroll
    for (int o = 1; o < NTHR; o <<= 1) {
        unsigned v = (t >= o) ? sh.su[t - o] : 0u;
        __syncthreads();
        sh.su[t] += v;
        __syncthreads();
    }
    unsigned incl = sh.su[t];
    unsigned exth = incl - hsum;             // exclusive within block
    if (t == NTHR - 1) g_bsum[blk] = incl;
    gbar(0);
    // redundant scan of the 64 block sums in every block
    __syncthreads();
    if (t < NBLK) sh.su[t] = __ldcg(&g_bsum[t]);
    __syncthreads();
#pragma unroll
    for (int o = 1; o < NBLK; o <<= 1) {
        unsigned v = (t >= o && t < NBLK) ? sh.su[t - o] : 0u;
        __syncthreads();
        if (t < NBLK) sh.su[t] += v;
        __syncthreads();
    }
    unsigned off0 = ((blk > 0) ? sh.su[blk - 1] : 0u) + exth;
    uint4 ov;
    ov.x = off0;
    ov.y = ov.x + hv.x;
    ov.z = ov.y + hv.y;
    ov.w = ov.z + hv.z;
    *(uint4*)&g_off[b0] = ov;
    gbar(1);

    // ---- Phase B: scatter packed (key,idx); 4 independent chains -----------
    {
        float4 kv = *(const float4*)&rank[b0];
        float kk[VT] = {kv.x, kv.y, kv.z, kv.w};
#pragma unroll
        for (int j = 0; j < VT; j++) {
            unsigned b = bucket_of(kk[j]);
            unsigned slot = __ldcg(&g_off[b]) + atomicAdd(&g_cnt[b], 1u);
            g_bsort[slot] = ((unsigned long long)__float_as_uint(kk[j]) << 32)
                            | (unsigned)(b0 + j);
        }
    }
    gbar(2);

    // ---- Phase C: within-bucket rank; write sorted e arrays; zero hist/cnt -
    {
        unsigned hj[VT]  = {hv.x, hv.y, hv.z, hv.w};
        unsigned offj[VT] = {ov.x, ov.y, ov.z, ov.w};
#pragma unroll
        for (int j = 0; j < VT; j++) {
            unsigned h = hj[j];
            if (h == 0u) continue;
            unsigned base = offj[j];
            if (h == 1u) {
                unsigned idx = (unsigned)(__ldcg(&g_bsort[base]) & 0xFFFFFFFFu);
                g_se2[base] = g_e2[idx];
                g_se3[base] = g_e3[idx];
            } else if (h <= 8u) {
                unsigned long long loc[8];
#pragma unroll
                for (int l = 0; l < 8; l++)
                    loc[l] = (l < (int)h) ? __ldcg(&g_bsort[base + l])
                                          : 0xFFFFFFFFFFFFFFFFull;   // sentinel: max
#pragma unroll
                for (int a2 = 0; a2 < 8; a2++) {
                    if (a2 < (int)h) {
                        unsigned long long kj = loc[a2];
                        unsigned r = 0;
#pragma unroll
                        for (int l = 0; l < 8; l++) r += (loc[l] < kj);
                        unsigned idx = (unsigned)(kj & 0xFFFFFFFFu);
                        g_se2[base + r] = g_e2[idx];
                        g_se3[base + r] = g_e3[idx];
                    }
                }
            } else {                          // extremely rare Poisson tail
                for (unsigned a2 = 0; a2 < h; a2++) {
                    unsigned long long kj = __ldcg(&g_bsort[base + a2]);
                    unsigned r = 0;
                    for (unsigned l = 0; l < h; l++)
                        r += (__ldcg(&g_bsort[base + l]) < kj);
                    unsigned idx = (unsigned)(kj & 0xFFFFFFFFu);
                    g_se2[base + r] = g_e2[idx];
                    g_se3[base + r] = g_e3[idx];
                }
            }
        }
        uint4 z = {0u, 0u, 0u, 0u};
        *(uint4*)&g_hist[b0] = z;             // cleanup for next call
        *(uint4*)&g_cnt[b0]  = z;
    }
    gbar(3);

    // ---- Phase D: per-chunk (1024-elem) double sums -------------------------
    float4 e2v = __ldcg((const float4*)&g_se2[b0]);
    float4 e3v = __ldcg((const float4*)&g_se3[b0]);
    double r2 = (double)e2v.x + (double)e2v.y + (double)e2v.z + (double)e2v.w;
    double r3 = (double)e3v.x + (double)e3v.y + (double)e3v.z + (double)e3v.w;
    {
        double a2 = r2, a3 = r3;
#pragma unroll
        for (int o = 16; o > 0; o >>= 1) {
            a2 += __shfl_xor_sync(0xFFFFFFFFu, a2, o);
            a3 += __shfl_xor_sync(0xFFFFFFFFu, a3, o);
        }
        if ((t & 31) == 0) { red8a[t >> 5] = a2; red8b[t >> 5] = a3; }
        __syncthreads();
        if (t == 0) {
            double s2 = 0.0, s3 = 0.0;
            for (int j = 0; j < 8; j++) { s2 += red8a[j]; s3 += red8b[j]; }
            g_csum2[blk] = s2; g_csum3[blk] = s3;
        }
    }
    gbar(4);

    // ---- Phase E: chunk-offset scan (redundant) + in-chunk prefix + logs ---
    __syncthreads();
    if (t < NBLK) { sh.dd.a[t] = __ldcg(&g_csum2[t]); sh.dd.b[t] = __ldcg(&g_csum3[t]); }
    __syncthreads();
#pragma unroll
    for (int o = 1; o < NBLK; o <<= 1) {
        double x2 = (t >= o && t < NBLK) ? sh.dd.a[t - o] : 0.0;
        double x3 = (t >= o && t < NBLK) ? sh.dd.b[t - o] : 0.0;
        __syncthreads();
        if (t < NBLK) { sh.dd.a[t] += x2; sh.dd.b[t] += x3; }
        __syncthreads();
    }
    double tot2 = sh.dd.a[NBLK - 1], tot3 = sh.dd.b[NBLK - 1];
    double coff2 = (blk > 0) ? sh.dd.a[blk - 1] : 0.0;
    double coff3 = (blk > 0) ? sh.dd.b[blk - 1] : 0.0;
    __syncthreads();

    // thread-local inclusive prefixes of the 4 elements
    double p2[VT], p3[VT];
    p2[0] = (double)e2v.x;            p3[0] = (double)e3v.x;
    p2[1] = p2[0] + (double)e2v.y;    p3[1] = p3[0] + (double)e3v.y;
    p2[2] = p2[1] + (double)e2v.z;    p3[2] = p3[1] + (double)e3v.z;
    p2[3] = p2[2] + (double)e2v.w;    p3[3] = p3[2] + (double)e3v.w;

    // block scan of per-thread totals (exclusive)
    sh.dd.a[t] = r2; sh.dd.b[t] = r3;
    __syncthreads();
#pragma unroll
    for (int o = 1; o < NTHR; o <<= 1) {
        double x2 = (t >= o) ? sh.dd.a[t - o] : 0.0;
        double x3 = (t >= o) ? sh.dd.b[t - o] : 0.0;
        __syncthreads();
        sh.dd.a[t] += x2; sh.dd.b[t] += x3;
        __syncthreads();
    }
    double base2 = coff2 + sh.dd.a[t] - r2;
    double base3 = coff3 + sh.dd.b[t] - r3;

    double ls = 0.0;
#pragma unroll
    for (int j = 0; j < VT; j++)
        ls += (double)logf((float)(base2 + p2[j])) +
              (double)logf((float)(base3 + p3[j]));
#pragma unroll
    for (int o = 16; o > 0; o >>= 1) ls += __shfl_xor_sync(0xFFFFFFFFu, ls, o);
    if ((t & 31) == 0) red8a[t >> 5] = ls;
    __syncthreads();
    if (t == 0) {
        double s = 0.0;
        for (int j = 0; j < 8; j++) s += red8a[j];
        g_part[blk] = s;
    }

    // ---- Final: last block reduces partials, writes out, resets state ------
    __shared__ bool amLast;
    if (t == 0) {
        __threadfence();
        amLast = (atomicAdd(&g_done, 1u) == NBLK - 1);
    }
    __syncthreads();
    if (amLast) {
        double p = (t < NBLK) ? __ldcg(&g_part[t]) : 0.0;
#pragma unroll
        for (int o = 16; o > 0; o >>= 1) p += __shfl_xor_sync(0xFFFFFFFFu, p, o);
        __syncthreads();
        if ((t & 31) == 0) red8a[t >> 5] = p;
        __syncthreads();
        if (t == 0) {
            double s = 0.0;
            for (int j = 0; j < 8; j++) s += red8a[j];
            out[0] = (float)((double)N_ROWS * (log(tot2) + log(tot3)) - s);
            g_done = 0u;                      // all blocks past final atomic; safe
        }
        if (t < 8) g_bar[t] = 0u;             // all blocks past all gbars; safe
    }
}

extern "C" void kernel_launch(void* const* d_in, const int* in_sizes, int n_in,
                              void* d_out, int out_size) {
    const float* o1   = (const float*)d_in[0];  // [65536, 512]
    const float* o2   = (const float*)d_in[1];  // [1, 512]
    const float* o3   = (const float*)d_in[2];  // [1, 512]
    const float* rank = (const float*)d_in[3];  // [65536]
    float* out = (float*)d_out;

    k1_main<<<N_ROWS / 8, 256>>>((const float4*)o1, (const float4*)o2,
                                 (const float4*)o3, rank);
    k2_fused<<<NBLK, NTHR>>>(rank, out);
}